// round 2
// baseline (speedup 1.0000x reference)
#include <cuda_runtime.h>
#include <cuda_bf16.h>

#define NT   320
#define KC   16
#define WPAD 210
#define WBUF (KC*WPAD)   // 3360 floats per W buffer
#define TBUF (KC*64)     // 1024 u64 entries per T buffer

typedef unsigned long long u64;

// ---- packed f32x2 helpers (sm_100a; ptxas never emits FFMA2 from C++) ----
__device__ __forceinline__ u64 ffma2(u64 a, u64 b, u64 c) {
    u64 d;
    asm("fma.rn.f32x2 %0, %1, %2, %3;" : "=l"(d) : "l"(a), "l"(b), "l"(c));
    return d;
}
__device__ __forceinline__ u64 pack2(float x, float y) {
    u64 d;
    asm("mov.b64 %0, {%1, %2};" : "=l"(d) : "f"(x), "f"(y));
    return d;
}
__device__ __forceinline__ void unpack2(u64 d, float& x, float& y) {
    asm("mov.b64 {%0, %1}, %2;" : "=f"(x), "=f"(y) : "l"(d));
}

// One layer: Y[200][64] = relu(W[200][K] @ T[K][64] + bias), T[c][d] = v[m][d]*src[n][d],
// c = m*Nh + n. First 100 rows -> h (next layer's src) unless LAST; direct rows summed
// over d into out.
template<int K, int Nh, int OUT_OFF, bool LAST>
__device__ __forceinline__ void layer_run(
    const float* __restrict__ Wg, const float* __restrict__ bg,
    float* __restrict__ v, float* __restrict__ h,
    float* __restrict__ Wt, u64* __restrict__ TS,
    float* __restrict__ out, int b, int tid)
{
    const int og = tid >> 4;   // 0..19 : o-tile of 10 -> o = og*10 + j
    const int dg = tid & 15;   // 0..15 : d set = {dg, dg+16, dg+32, dg+48}
    const float* src = (Nh == 40) ? v : h;

    u64 acc[4][5];             // acc[dd][jp] : d = dg+16*dd, o pair = og*10 + 2*jp {lo,hi}
    #pragma unroll
    for (int dd = 0; dd < 4; dd++)
        #pragma unroll
        for (int jp = 0; jp < 5; jp++) acc[dd][jp] = 0ull;

    constexpr int NCH = K / KC;

    // ---- stage chunk 0 into buffer 0 ----
    {
        float wreg[10];
        #pragma unroll
        for (int i = 0; i < 10; i++) {
            int idx = tid + i*NT;                       // 0..3199 = 200 o x 16 kk
            wreg[i] = Wg[(idx >> 4)*K + (idx & 15)];
        }
        for (int idx = tid; idx < KC*64; idx += NT) {   // T chunk: splatted pairs
            int c = idx >> 6, d = idx & 63;
            int m = c / Nh, n = c % Nh;
            float p = v[m*64 + d] * src[n*64 + d];
            TS[idx] = pack2(p, p);
        }
        #pragma unroll
        for (int i = 0; i < 10; i++) {
            int idx = tid + i*NT;
            Wt[(idx & 15)*WPAD + (idx >> 4)] = wreg[i]; // transposed, pad 210: conflict-free
        }
    }
    __syncthreads();

    for (int kc = 0; kc < NCH; kc++) {
        const int cur = kc & 1, nxt = cur ^ 1;
        const bool more = (kc + 1) < NCH;

        // issue next chunk's global W loads early; latency hidden by compute below
        float wreg[10];
        if (more) {
            const int k0n = (kc + 1) * KC;
            #pragma unroll
            for (int i = 0; i < 10; i++) {
                int idx = tid + i*NT;
                wreg[i] = Wg[(idx >> 4)*K + k0n + (idx & 15)];
            }
        }

        // ---- compute current chunk: per kk: 5 LDS.64 (W) + 4 LDS.64 (T) + 20 FFMA2 ----
        const float* Wc = Wt + cur*WBUF;
        const u64*   Tc = TS + cur*TBUF;
        #pragma unroll
        for (int kk = 0; kk < KC; kk++) {
            const u64* wp = reinterpret_cast<const u64*>(Wc + kk*WPAD + og*10);
            u64 w[5];
            #pragma unroll
            for (int jp = 0; jp < 5; jp++) w[jp] = wp[jp];
            const u64* tp = Tc + kk*64 + dg;
            u64 t[4];
            #pragma unroll
            for (int dd = 0; dd < 4; dd++) t[dd] = tp[dd*16];
            #pragma unroll
            for (int dd = 0; dd < 4; dd++)
                #pragma unroll
                for (int jp = 0; jp < 5; jp++)
                    acc[dd][jp] = ffma2(w[jp], t[dd], acc[dd][jp]);
        }

        // ---- stage next chunk into the other buffer ----
        if (more) {
            const int k0n = (kc + 1) * KC;
            u64* Tn = TS + nxt*TBUF;
            for (int idx = tid; idx < KC*64; idx += NT) {
                int kk = idx >> 6, d = idx & 63;
                int c = k0n + kk;
                int m = c / Nh, n = c % Nh;
                float p = v[m*64 + d] * src[n*64 + d];
                Tn[idx] = pack2(p, p);
            }
            float* Wn = Wt + nxt*WBUF;
            #pragma unroll
            for (int i = 0; i < 10; i++) {
                int idx = tid + i*NT;
                Wn[(idx & 15)*WPAD + (idx >> 4)] = wreg[i];
            }
        }
        __syncthreads();
    }

    // ---- epilogue: bias + relu, write h, reduce over d, write direct outputs ----
    float y[4][10];
    #pragma unroll
    for (int jp = 0; jp < 5; jp++) {
        float blo = bg[og*10 + 2*jp];
        float bhi = bg[og*10 + 2*jp + 1];
        #pragma unroll
        for (int dd = 0; dd < 4; dd++) {
            float lo, hi;
            unpack2(acc[dd][jp], lo, hi);
            y[dd][2*jp]     = fmaxf(lo + blo, 0.0f);
            y[dd][2*jp + 1] = fmaxf(hi + bhi, 0.0f);
        }
    }
    if (!LAST && og < 10) {           // rows 0..99 become next hidden
        #pragma unroll
        for (int j = 0; j < 10; j++)
            #pragma unroll
            for (int dd = 0; dd < 4; dd++)
                h[(og*10 + j)*64 + dg + 16*dd] = y[dd][j];
    }
    #pragma unroll
    for (int j = 0; j < 10; j++) {    // sum over the 64 d values (4 local + 16 lanes)
        float s = y[0][j] + y[1][j] + y[2][j] + y[3][j];
        s += __shfl_xor_sync(0xFFFFFFFFu, s, 8);
        s += __shfl_xor_sync(0xFFFFFFFFu, s, 4);
        s += __shfl_xor_sync(0xFFFFFFFFu, s, 2);
        s += __shfl_xor_sync(0xFFFFFFFFu, s, 1);
        if (dg == 0) {
            int o = og*10 + j;
            if (LAST)          out[b*400 + 200 + o] = s;
            else if (o >= 100) out[b*400 + OUT_OFF + (o - 100)] = s;
        }
    }
    __syncthreads();   // h fully written before next layer stages T from it
}

__global__ void __launch_bounds__(NT, 2)
_CIN_41575283425691_kernel(const float* __restrict__ x,
                           const float* __restrict__ w1, const float* __restrict__ b1,
                           const float* __restrict__ w2, const float* __restrict__ b2,
                           const float* __restrict__ w3, const float* __restrict__ b3,
                           float* __restrict__ out)
{
    extern __shared__ float sm[];
    float* v  = sm;                                    // 40 x 64            = 2560 f
    float* h  = sm + 2560;                             // 100 x 64           = 6400 f
    float* Wt = sm + 8960;                             // 2 x 16 x 210       = 6720 f
    u64*  TS  = reinterpret_cast<u64*>(sm + 15680);    // 2 x 1024 x 8B      = 16384 B

    const int tid = threadIdx.x;
    const int b   = blockIdx.x;

    const float* xb = x + b*2560;
    for (int i = tid; i < 2560; i += NT) v[i] = xb[i];
    __syncthreads();

    layer_run<1600,  40,   0, false>(w1, b1, v, h, Wt, TS, out, b, tid);
    layer_run<4000, 100, 100, false>(w2, b2, v, h, Wt, TS, out, b, tid);
    layer_run<4000, 100,   0, true >(w3, b3, v, h, Wt, TS, out, b, tid);
}

#define SMEM_BYTES 79104   // 15680 floats + 16384 B = 62720 + 16384

extern "C" void kernel_launch(void* const* d_in, const int* in_sizes, int n_in,
                              void* d_out, int out_size)
{
    const float* x  = (const float*)d_in[0];
    const float* w1 = (const float*)d_in[1];
    const float* b1 = (const float*)d_in[2];
    const float* w2 = (const float*)d_in[3];
    const float* b2 = (const float*)d_in[4];
    const float* w3 = (const float*)d_in[5];
    const float* b3 = (const float*)d_in[6];
    float* out = (float*)d_out;

    cudaFuncSetAttribute(_CIN_41575283425691_kernel,
                         cudaFuncAttributeMaxDynamicSharedMemorySize, SMEM_BYTES);
    _CIN_41575283425691_kernel<<<512, NT, SMEM_BYTES>>>(x, w1, b1, w2, b2, w3, b3, out);
}

// round 3
// speedup vs baseline: 1.0001x; 1.0001x over previous
#include <cuda_runtime.h>
#include <cuda_bf16.h>

#define NT   320
#define KC   16
#define WPAD 210
#define WBUF (KC*WPAD)   // 3360 floats per W buffer
#define TBUF (KC*64)     // 1024 u64 entries per T buffer

typedef unsigned long long u64;

// ---- packed f32x2 helpers (sm_100a; ptxas never emits FFMA2 from C++) ----
__device__ __forceinline__ u64 ffma2(u64 a, u64 b, u64 c) {
    u64 d;
    asm("fma.rn.f32x2 %0, %1, %2, %3;" : "=l"(d) : "l"(a), "l"(b), "l"(c));
    return d;
}
__device__ __forceinline__ u64 pack2(float x, float y) {
    u64 d;
    asm("mov.b64 %0, {%1, %2};" : "=l"(d) : "f"(x), "f"(y));
    return d;
}
__device__ __forceinline__ void unpack2(u64 d, float& x, float& y) {
    asm("mov.b64 {%0, %1}, %2;" : "=f"(x), "=f"(y) : "l"(d));
}

// One layer: Y[200][64] = relu(W[200][K] @ T[K][64] + bias), T[c][d] = v[m][d]*src[n][d],
// c = m*Nh + n. First 100 rows -> h (next layer's src) unless LAST; direct rows summed
// over d into out.
template<int K, int Nh, int OUT_OFF, bool LAST>
__device__ __forceinline__ void layer_run(
    const float* __restrict__ Wg, const float* __restrict__ bg,
    float* __restrict__ v, float* __restrict__ h,
    float* __restrict__ Wt, u64* __restrict__ TS,
    float* __restrict__ out, int b, int tid)
{
    const int og = tid >> 4;   // 0..19 : o-tile of 10 -> o = og*10 + j
    const int dg = tid & 15;   // 0..15 : d set = {dg, dg+16, dg+32, dg+48}
    const float* src = (Nh == 40) ? v : h;

    u64 acc[4][5];             // acc[dd][jp] : d = dg+16*dd, o pair = og*10 + 2*jp {lo,hi}
    #pragma unroll
    for (int dd = 0; dd < 4; dd++)
        #pragma unroll
        for (int jp = 0; jp < 5; jp++) acc[dd][jp] = 0ull;

    constexpr int NCH = K / KC;

    // ---- stage chunk 0 into buffer 0 ----
    {
        float wreg[10];
        #pragma unroll
        for (int i = 0; i < 10; i++) {
            int idx = tid + i*NT;                       // 0..3199 = 200 o x 16 kk
            wreg[i] = Wg[(idx >> 4)*K + (idx & 15)];
        }
        for (int idx = tid; idx < KC*64; idx += NT) {   // T chunk: splatted pairs
            int c = idx >> 6, d = idx & 63;
            int m = c / Nh, n = c % Nh;
            float p = v[m*64 + d] * src[n*64 + d];
            TS[idx] = pack2(p, p);
        }
        #pragma unroll
        for (int i = 0; i < 10; i++) {
            int idx = tid + i*NT;
            Wt[(idx & 15)*WPAD + (idx >> 4)] = wreg[i]; // transposed, pad 210: conflict-free
        }
    }
    __syncthreads();

    for (int kc = 0; kc < NCH; kc++) {
        const int cur = kc & 1, nxt = cur ^ 1;
        const bool more = (kc + 1) < NCH;

        // issue next chunk's global W loads early; latency hidden by compute below
        float wreg[10];
        if (more) {
            const int k0n = (kc + 1) * KC;
            #pragma unroll
            for (int i = 0; i < 10; i++) {
                int idx = tid + i*NT;
                wreg[i] = Wg[(idx >> 4)*K + k0n + (idx & 15)];
            }
        }

        // ---- compute current chunk: per kk: 5 LDS.64 (W) + 4 LDS.64 (T) + 20 FFMA2 ----
        const float* Wc = Wt + cur*WBUF;
        const u64*   Tc = TS + cur*TBUF;
        #pragma unroll
        for (int kk = 0; kk < KC; kk++) {
            const u64* wp = reinterpret_cast<const u64*>(Wc + kk*WPAD + og*10);
            u64 w[5];
            #pragma unroll
            for (int jp = 0; jp < 5; jp++) w[jp] = wp[jp];
            const u64* tp = Tc + kk*64 + dg;
            u64 t[4];
            #pragma unroll
            for (int dd = 0; dd < 4; dd++) t[dd] = tp[dd*16];
            #pragma unroll
            for (int dd = 0; dd < 4; dd++)
                #pragma unroll
                for (int jp = 0; jp < 5; jp++)
                    acc[dd][jp] = ffma2(w[jp], t[dd], acc[dd][jp]);
        }

        // ---- stage next chunk into the other buffer ----
        if (more) {
            const int k0n = (kc + 1) * KC;
            u64* Tn = TS + nxt*TBUF;
            for (int idx = tid; idx < KC*64; idx += NT) {
                int kk = idx >> 6, d = idx & 63;
                int c = k0n + kk;
                int m = c / Nh, n = c % Nh;
                float p = v[m*64 + d] * src[n*64 + d];
                Tn[idx] = pack2(p, p);
            }
            float* Wn = Wt + nxt*WBUF;
            #pragma unroll
            for (int i = 0; i < 10; i++) {
                int idx = tid + i*NT;
                Wn[(idx & 15)*WPAD + (idx >> 4)] = wreg[i];
            }
        }
        __syncthreads();
    }

    // ---- epilogue: bias + relu, write h, reduce over d, write direct outputs ----
    float y[4][10];
    #pragma unroll
    for (int jp = 0; jp < 5; jp++) {
        float blo = bg[og*10 + 2*jp];
        float bhi = bg[og*10 + 2*jp + 1];
        #pragma unroll
        for (int dd = 0; dd < 4; dd++) {
            float lo, hi;
            unpack2(acc[dd][jp], lo, hi);
            y[dd][2*jp]     = fmaxf(lo + blo, 0.0f);
            y[dd][2*jp + 1] = fmaxf(hi + bhi, 0.0f);
        }
    }
    if (!LAST && og < 10) {           // rows 0..99 become next hidden
        #pragma unroll
        for (int j = 0; j < 10; j++)
            #pragma unroll
            for (int dd = 0; dd < 4; dd++)
                h[(og*10 + j)*64 + dg + 16*dd] = y[dd][j];
    }
    #pragma unroll
    for (int j = 0; j < 10; j++) {    // sum over the 64 d values (4 local + 16 lanes)
        float s = y[0][j] + y[1][j] + y[2][j] + y[3][j];
        s += __shfl_xor_sync(0xFFFFFFFFu, s, 8);
        s += __shfl_xor_sync(0xFFFFFFFFu, s, 4);
        s += __shfl_xor_sync(0xFFFFFFFFu, s, 2);
        s += __shfl_xor_sync(0xFFFFFFFFu, s, 1);
        if (dg == 0) {
            int o = og*10 + j;
            if (LAST)          out[b*400 + 200 + o] = s;
            else if (o >= 100) out[b*400 + OUT_OFF + (o - 100)] = s;
        }
    }
    __syncthreads();   // h fully written before next layer stages T from it
}

__global__ void __launch_bounds__(NT, 2)
_CIN_41575283425691_kernel(const float* __restrict__ x,
                           const float* __restrict__ w1, const float* __restrict__ b1,
                           const float* __restrict__ w2, const float* __restrict__ b2,
                           const float* __restrict__ w3, const float* __restrict__ b3,
                           float* __restrict__ out)
{
    extern __shared__ float sm[];
    float* v  = sm;                                    // 40 x 64            = 2560 f
    float* h  = sm + 2560;                             // 100 x 64           = 6400 f
    float* Wt = sm + 8960;                             // 2 x 16 x 210       = 6720 f
    u64*  TS  = reinterpret_cast<u64*>(sm + 15680);    // 2 x 1024 x 8B      = 16384 B

    const int tid = threadIdx.x;
    const int b   = blockIdx.x;

    const float* xb = x + b*2560;
    for (int i = tid; i < 2560; i += NT) v[i] = xb[i];
    __syncthreads();

    layer_run<1600,  40,   0, false>(w1, b1, v, h, Wt, TS, out, b, tid);
    layer_run<4000, 100, 100, false>(w2, b2, v, h, Wt, TS, out, b, tid);
    layer_run<4000, 100,   0, true >(w3, b3, v, h, Wt, TS, out, b, tid);
}

#define SMEM_BYTES 79104   // 15680 floats + 16384 B = 62720 + 16384

extern "C" void kernel_launch(void* const* d_in, const int* in_sizes, int n_in,
                              void* d_out, int out_size)
{
    const float* x  = (const float*)d_in[0];
    const float* w1 = (const float*)d_in[1];
    const float* b1 = (const float*)d_in[2];
    const float* w2 = (const float*)d_in[3];
    const float* b2 = (const float*)d_in[4];
    const float* w3 = (const float*)d_in[5];
    const float* b3 = (const float*)d_in[6];
    float* out = (float*)d_out;

    cudaFuncSetAttribute(_CIN_41575283425691_kernel,
                         cudaFuncAttributeMaxDynamicSharedMemorySize, SMEM_BYTES);
    _CIN_41575283425691_kernel<<<512, NT, SMEM_BYTES>>>(x, w1, b1, w2, b2, w3, b3, out);
}